// round 12
// baseline (speedup 1.0000x reference)
#include <cuda_runtime.h>
#include <cuda_bf16.h>
#include <cstdint>
#include <cstddef>

// out[8192,4096] = x[8192,4096] @ (W .* mask)^T + bias  (fp32 in/out)
// R12: HMMA with fully precomputed bf16 hi/lo fragment streams.
//  - prepx: x -> bf16 hi/lo planes (once per launch)
//  - packw: active W blocks -> per-lane MMA fragments, compacted stream order
//  - gemm: zero-smem, zero-cvt inner loop; flat prefetched B stream
#define MTOT 8192
#define KDIM 4096
#define NDIM 4096
#define NBK  256       // 16-wide K blocks
#define NGRP 32        // groups of 8 out-blocks (128 cols each)
#define KW   2048      // uint32 (bf16-pair) per x row
#define MAXSLOT 2048   // max active blocks per group (8 obs x 256 kbs)

// ---------------- device scratch ----------------
__device__ int           g_flagmask;
__device__ int           g_kn[NGRP];
__device__ int           g_stot[NGRP];
__device__ unsigned char g_klist[NGRP][NBK];   // compacted active kb indices
__device__ unsigned char g_actL[NGRP][NBK];    // 8-bit ob activity, list order
__device__ int           g_sbase[NGRP][NBK];   // slot base per list entry
__device__ unsigned      g_xh[(size_t)MTOT * KW];   // x hi plane (64MB)
__device__ unsigned      g_xl[(size_t)MTOT * KW];   // x lo plane (64MB)
__device__ uint4         g_wf[(size_t)NGRP * MAXSLOT * 64];  // W fragments (64MB)

// ---------------- helpers ----------------
static __device__ __forceinline__ void cvtpair(float2 v, unsigned& hi, unsigned& lo) {
    asm("cvt.rn.bf16x2.f32 %0, %1, %2;" : "=r"(hi) : "f"(v.y), "f"(v.x));
    float h0 = __uint_as_float(hi << 16);
    float h1 = __uint_as_float(hi & 0xFFFF0000u);
    float l0 = v.x - h0;
    float l1 = v.y - h1;
    asm("cvt.rn.bf16x2.f32 %0, %1, %2;" : "=r"(lo) : "f"(l1), "f"(l0));
}
static __device__ __forceinline__ int nth_bit(unsigned m, int n) {
    for (int j = 0; j < n; j++) m &= m - 1;
    return __ffs(m) - 1;
}
#define MMA16816(c, A, b0, b1) \
    asm volatile("mma.sync.aligned.m16n8k16.row.col.f32.bf16.bf16.f32 " \
        "{%0,%1,%2,%3},{%4,%5,%6,%7},{%8,%9},{%0,%1,%2,%3};" \
        : "+f"((c)[0]), "+f"((c)[1]), "+f"((c)[2]), "+f"((c)[3]) \
        : "r"((A)[0]), "r"((A)[1]), "r"((A)[2]), "r"((A)[3]), "r"(b0), "r"(b1))

// ---------------- 0) reset flags ----------------
__global__ void init_kernel() { if (threadIdx.x == 0) g_flagmask = 0; }

// ---------------- 1) mask dtype detection (4MB window) ----------------
__global__ void detect_kernel(const unsigned int* __restrict__ m) {
    unsigned int w = m[(size_t)blockIdx.x * blockDim.x + threadIdx.x];
    unsigned int f = 0u;
    if (w == 0x3F800000u) f |= 1u;
    if (w == 0x3F803F80u) f |= 2u;
    if (w == 0x01010101u) f |= 4u;
    if (w == 0x00000001u) f |= 8u;
    f = __reduce_or_sync(0xFFFFFFFFu, f);
    __shared__ unsigned int sf;
    if (threadIdx.x == 0) sf = 0u;
    __syncthreads();
    if ((threadIdx.x & 31) == 0 && f) atomicOr(&sf, f);
    __syncthreads();
    if (threadIdx.x == 0 && sf) atomicOr((unsigned int*)&g_flagmask, (int)sf);
}

// ---------------- 2) build compacted activity lists + slot bases ----------------
__global__ void build_kernel(const void* __restrict__ mask) {
    int g = blockIdx.x, kb = threadIdx.x;
    int fl = g_flagmask;
    unsigned m = 0;
    for (int a = 0; a < 8; a++) {
        size_t e = (size_t)((g * 8 + a) * 16) * KDIM + (size_t)kb * 16;
        bool v;
        if (fl & 1)      v = ((const float*)mask)[e] != 0.0f;
        else if (fl & 2) v = ((const unsigned short*)mask)[e] != 0;
        else if (fl & 4) v = ((const unsigned char*)mask)[e] != 0;
        else             v = ((const int*)mask)[e] != 0;
        if (v) m |= 1u << a;
    }
    __shared__ unsigned sact[NBK];
    sact[kb] = m;
    __syncthreads();
    if (kb == 0) {
        int n = 0, s = 0;
        #pragma unroll 1
        for (int k = 0; k < NBK; k++) {
            if (sact[k]) {
                g_klist[g][n] = (unsigned char)k;
                g_actL[g][n]  = (unsigned char)sact[k];
                g_sbase[g][n] = s;
                s += __popc(sact[k]);
                n++;
            }
        }
        g_kn[g] = n;
        g_stot[g] = s;
    }
}

// ---------------- 3) pre-split x into bf16 hi/lo planes ----------------
// block = row; thread handles 8 uint32 (16 floats).
__global__ void prepx_kernel(const float* __restrict__ x) {
    int row = blockIdx.x, tid = threadIdx.x;
    const float4* src = (const float4*)(x + (size_t)row * KDIM + tid * 16);
    float4 v0 = __ldg(src), v1 = __ldg(src + 1), v2 = __ldg(src + 2), v3 = __ldg(src + 3);
    unsigned h[8], l[8];
    cvtpair(make_float2(v0.x, v0.y), h[0], l[0]);
    cvtpair(make_float2(v0.z, v0.w), h[1], l[1]);
    cvtpair(make_float2(v1.x, v1.y), h[2], l[2]);
    cvtpair(make_float2(v1.z, v1.w), h[3], l[3]);
    cvtpair(make_float2(v2.x, v2.y), h[4], l[4]);
    cvtpair(make_float2(v2.z, v2.w), h[5], l[5]);
    cvtpair(make_float2(v3.x, v3.y), h[6], l[6]);
    cvtpair(make_float2(v3.z, v3.w), h[7], l[7]);
    uint4* dh = (uint4*)(g_xh + (size_t)row * KW + tid * 8);
    uint4* dl = (uint4*)(g_xl + (size_t)row * KW + tid * 8);
    dh[0] = make_uint4(h[0], h[1], h[2], h[3]);
    dh[1] = make_uint4(h[4], h[5], h[6], h[7]);
    dl[0] = make_uint4(l[0], l[1], l[2], l[3]);
    dl[1] = make_uint4(l[4], l[5], l[6], l[7]);
}

// ---------------- 4) pack active W blocks into fragment stream ----------------
// block = (g, i). Warp w packs slot sbase+w (the w-th active ob of entry i).
// Per lane: 4 fragment uint32 hi + 4 lo = exactly the mma.sync B registers
// for both n8 tiles: {nt0 k0-7, nt0 k8-15, nt1 k0-7, nt1 k8-15}.
__global__ void packw_kernel(const float* __restrict__ wt) {
    int g = blockIdx.x, i = blockIdx.y;
    if (i >= g_kn[g]) return;
    int w = threadIdx.x >> 5, lane = threadIdx.x & 31;
    unsigned act = g_actL[g][i];
    if (w >= __popc(act)) return;
    int a = nth_bit(act, w);
    int kb = g_klist[g][i];
    int slot = g_sbase[g][i] + w;
    int qr = lane >> 2, qk = (lane & 3) * 2;

    const float* base = wt + (size_t)(g * 128 + a * 16 + qr) * KDIM + kb * 16 + qk;
    float2 f00 = __ldg((const float2*)base);                        // nt0, k0-7
    float2 f01 = __ldg((const float2*)(base + 8));                  // nt0, k8-15
    float2 f10 = __ldg((const float2*)(base + 8 * KDIM));           // nt1, k0-7
    float2 f11 = __ldg((const float2*)(base + 8 * KDIM + 8));       // nt1, k8-15
    unsigned h0, l0, h1, l1, h2, l2, h3, l3;
    cvtpair(f00, h0, l0);
    cvtpair(f01, h1, l1);
    cvtpair(f10, h2, l2);
    cvtpair(f11, h3, l3);
    uint4* dst = g_wf + ((size_t)g * MAXSLOT + slot) * 64;
    dst[lane]      = make_uint4(h0, h1, h2, h3);
    dst[32 + lane] = make_uint4(l0, l1, l2, l3);
}

// ---------------- 5) block-sparse HMMA GEMM (zero smem, zero cvt) ----------------
__global__ void __launch_bounds__(256, 2) gemm_kernel(
    const float* __restrict__ bias, float* __restrict__ out)
{
    int tid = threadIdx.x, w = tid >> 5, lane = tid & 31;
    int g = blockIdx.x, m0 = blockIdx.y << 7;
    int qr = lane >> 2, q = lane & 3, qk = q * 2;

    float C[8][2][4];
    #pragma unroll
    for (int a = 0; a < 8; a++)
        #pragma unroll
        for (int nt = 0; nt < 2; nt++)
            #pragma unroll
            for (int qq = 0; qq < 4; qq++) C[a][nt][qq] = 0.0f;

    int kn = g_kn[g];
    int stot = g_stot[g];

    // A plane pointers: rows r0 = m0 + w*16 + qr and r0+8
    const unsigned* xh0 = g_xh + (size_t)(m0 + w * 16 + qr) * KW + q;
    const unsigned* xh1 = xh0 + (size_t)8 * KW;
    const unsigned* xl0 = g_xl + (size_t)(m0 + w * 16 + qr) * KW + q;
    const unsigned* xl1 = xl0 + (size_t)8 * KW;
    const uint4* wf = g_wf + (size_t)g * MAXSLOT * 64;

    unsigned ah[4], al[4], nah[4], nal[4];
    uint4 pbh, pbl;
    if (kn > 0) {
        int o = (int)g_klist[g][0] * 8;
        ah[0] = __ldg(xh0 + o); ah[1] = __ldg(xh1 + o);
        ah[2] = __ldg(xh0 + o + 4); ah[3] = __ldg(xh1 + o + 4);
        al[0] = __ldg(xl0 + o); al[1] = __ldg(xl1 + o);
        al[2] = __ldg(xl0 + o + 4); al[3] = __ldg(xl1 + o + 4);
        pbh = __ldg(wf + lane);
        pbl = __ldg(wf + 32 + lane);
    }

    int t = 0;
    for (int i = 0; i < kn; i++) {
        unsigned act = g_actL[g][i];

        // ---- prefetch next iteration's A fragments ----
        if (i + 1 < kn) {
            int no = (int)g_klist[g][i + 1] * 8;
            nah[0] = __ldg(xh0 + no); nah[1] = __ldg(xh1 + no);
            nah[2] = __ldg(xh0 + no + 4); nah[3] = __ldg(xh1 + no + 4);
            nal[0] = __ldg(xl0 + no); nal[1] = __ldg(xl1 + no);
            nal[2] = __ldg(xl0 + no + 4); nal[3] = __ldg(xl1 + no + 4);
        }

        // ---- per active ob: prefetched B fragment + 6 MMAs ----
        #pragma unroll
        for (int a = 0; a < 8; a++) {
            if ((act >> a) & 1) {
                uint4 bh = pbh, bl = pbl;
                if (t + 1 < stot) {
                    pbh = __ldg(wf + (size_t)(t + 1) * 64 + lane);
                    pbl = __ldg(wf + (size_t)(t + 1) * 64 + 32 + lane);
                }
                MMA16816(C[a][0], ah, bh.x, bh.y);
                MMA16816(C[a][0], al, bh.x, bh.y);
                MMA16816(C[a][0], ah, bl.x, bl.y);
                MMA16816(C[a][1], ah, bh.z, bh.w);
                MMA16816(C[a][1], al, bh.z, bh.w);
                MMA16816(C[a][1], ah, bl.z, bl.w);
                t++;
            }
        }

        #pragma unroll
        for (int j = 0; j < 4; j++) { ah[j] = nah[j]; al[j] = nal[j]; }
    }

    // ---- epilogue: bias + store ----
    {
        int r0 = m0 + w * 16 + qr;
        const float* bg = bias + g * 128;
        #pragma unroll
        for (int a = 0; a < 8; a++) {
            #pragma unroll
            for (int nt = 0; nt < 2; nt++) {
                int col = a * 16 + nt * 8 + qk;
                float2 bv = __ldg((const float2*)(bg + col));
                size_t gc = (size_t)g * 128 + col;
                float2 v0 = make_float2(C[a][nt][0] + bv.x, C[a][nt][1] + bv.y);
                float2 v1 = make_float2(C[a][nt][2] + bv.x, C[a][nt][3] + bv.y);
                *(float2*)(out + (size_t)r0 * NDIM + gc)       = v0;
                *(float2*)(out + (size_t)(r0 + 8) * NDIM + gc) = v1;
            }
        }
    }
}

// ---------------- launch ----------------
extern "C" void kernel_launch(void* const* d_in, const int* in_sizes, int n_in,
                              void* d_out, int out_size)
{
    const float* x    = (const float*)d_in[0];
    const float* wt   = (const float*)d_in[1];
    const float* bias = (const float*)d_in[2];
    const void*  mask = d_in[3];
    float*       out  = (float*)d_out;

    init_kernel<<<1, 32>>>();
    detect_kernel<<<4096, 256>>>((const unsigned int*)mask);
    build_kernel<<<NGRP, NBK>>>(mask);
    prepx_kernel<<<MTOT, 256>>>(x);
    packw_kernel<<<dim3(NGRP, NBK), 256>>>(wt);
    gemm_kernel<<<dim3(NGRP, MTOT / 128), 256>>>(bias, out);
}

// round 14
// speedup vs baseline: 1.2264x; 1.2264x over previous
#include <cuda_runtime.h>
#include <cuda_bf16.h>
#include <cstdint>
#include <cstddef>

// out[8192,4096] = x[8192,4096] @ (W .* mask)^T + bias  (fp32 in/out)
// R14 (= R13 resubmit after infra failure): HMMA, warp tile 32 rows x 4 obs,
// per-half compacted k-lists, x packed as interleaved (hi,lo) bf16-pair stream,
// W fragment streams per half. Zero smem, zero cvt in the GEMM loop.
#define MTOT 8192
#define KDIM 4096
#define NDIM 4096
#define NBK  256       // 16-wide K blocks
#define NGRP 32        // groups of 8 out-blocks (128 cols each)
#define KW   2048      // bf16 pairs per x row
#define MAXSH 1024     // max active blocks per (group, half)

// ---------------- device scratch ----------------
__device__ int           g_flagmask;
__device__ int           g_knH[NGRP][2];
__device__ int           g_stotH[NGRP][2];
__device__ unsigned char g_klistH[NGRP][2][NBK];
__device__ unsigned char g_actH[NGRP][2][NBK];    // 4-bit ob activity within half
__device__ short         g_sbaseH[NGRP][2][NBK];
__device__ uint2         g_xp[(size_t)MTOT * KW];              // (hi,lo) per pair, 128MB
__device__ uint4         g_wfH[(size_t)NGRP * 2 * MAXSH * 64]; // W fragments, 64MB

// ---------------- helpers ----------------
static __device__ __forceinline__ void cvtpair(float2 v, unsigned& hi, unsigned& lo) {
    asm("cvt.rn.bf16x2.f32 %0, %1, %2;" : "=r"(hi) : "f"(v.y), "f"(v.x));
    float h0 = __uint_as_float(hi << 16);
    float h1 = __uint_as_float(hi & 0xFFFF0000u);
    float l0 = v.x - h0;
    float l1 = v.y - h1;
    asm("cvt.rn.bf16x2.f32 %0, %1, %2;" : "=r"(lo) : "f"(l1), "f"(l0));
}
static __device__ __forceinline__ int nth_bit(unsigned m, int n) {
    for (int j = 0; j < n; j++) m &= m - 1;
    return __ffs(m) - 1;
}
#define MMA16816R(c, a0, a1, a2, a3, b0, b1) \
    asm volatile("mma.sync.aligned.m16n8k16.row.col.f32.bf16.bf16.f32 " \
        "{%0,%1,%2,%3},{%4,%5,%6,%7},{%8,%9},{%0,%1,%2,%3};" \
        : "+f"((c)[0]), "+f"((c)[1]), "+f"((c)[2]), "+f"((c)[3]) \
        : "r"(a0), "r"(a1), "r"(a2), "r"(a3), "r"(b0), "r"(b1))

// ---------------- 0) reset flags ----------------
__global__ void init_kernel() { if (threadIdx.x == 0) g_flagmask = 0; }

// ---------------- 1) mask dtype detection (4MB window) ----------------
__global__ void detect_kernel(const unsigned int* __restrict__ m) {
    unsigned int w = m[(size_t)blockIdx.x * blockDim.x + threadIdx.x];
    unsigned int f = 0u;
    if (w == 0x3F800000u) f |= 1u;
    if (w == 0x3F803F80u) f |= 2u;
    if (w == 0x01010101u) f |= 4u;
    if (w == 0x00000001u) f |= 8u;
    f = __reduce_or_sync(0xFFFFFFFFu, f);
    __shared__ unsigned int sf;
    if (threadIdx.x == 0) sf = 0u;
    __syncthreads();
    if ((threadIdx.x & 31) == 0 && f) atomicOr(&sf, f);
    __syncthreads();
    if (threadIdx.x == 0 && sf) atomicOr((unsigned int*)&g_flagmask, (int)sf);
}

// ---------------- 2) build per-half compacted lists ----------------
__global__ void build_kernel(const void* __restrict__ mask) {
    int g = blockIdx.x, kb = threadIdx.x;
    int fl = g_flagmask;
    unsigned m = 0;
    for (int a = 0; a < 8; a++) {
        size_t e = (size_t)((g * 8 + a) * 16) * KDIM + (size_t)kb * 16;
        bool v;
        if (fl & 1)      v = ((const float*)mask)[e] != 0.0f;
        else if (fl & 2) v = ((const unsigned short*)mask)[e] != 0;
        else if (fl & 4) v = ((const unsigned char*)mask)[e] != 0;
        else             v = ((const int*)mask)[e] != 0;
        if (v) m |= 1u << a;
    }
    __shared__ unsigned sact[NBK];
    sact[kb] = m;
    __syncthreads();
    if (kb == 0) {
        for (int h = 0; h < 2; h++) {
            int n = 0, s = 0;
            #pragma unroll 1
            for (int k = 0; k < NBK; k++) {
                unsigned ah = (sact[k] >> (h * 4)) & 0xFu;
                if (ah) {
                    g_klistH[g][h][n] = (unsigned char)k;
                    g_actH[g][h][n]   = (unsigned char)ah;
                    g_sbaseH[g][h][n] = (short)s;
                    s += __popc(ah);
                    n++;
                }
            }
            g_knH[g][h] = n;
            g_stotH[g][h] = s;
        }
    }
}

// ---------------- 3) pre-split x into interleaved (hi,lo) pair stream ----------------
// block = row; thread handles 8 pairs (16 floats).
__global__ void prepx_kernel(const float* __restrict__ x) {
    int row = blockIdx.x, tid = threadIdx.x;
    const float4* src = (const float4*)(x + (size_t)row * KDIM + tid * 16);
    float4 v0 = __ldg(src), v1 = __ldg(src + 1), v2 = __ldg(src + 2), v3 = __ldg(src + 3);
    unsigned h[8], l[8];
    cvtpair(make_float2(v0.x, v0.y), h[0], l[0]);
    cvtpair(make_float2(v0.z, v0.w), h[1], l[1]);
    cvtpair(make_float2(v1.x, v1.y), h[2], l[2]);
    cvtpair(make_float2(v1.z, v1.w), h[3], l[3]);
    cvtpair(make_float2(v2.x, v2.y), h[4], l[4]);
    cvtpair(make_float2(v2.z, v2.w), h[5], l[5]);
    cvtpair(make_float2(v3.x, v3.y), h[6], l[6]);
    cvtpair(make_float2(v3.z, v3.w), h[7], l[7]);
    uint4* d = (uint4*)(g_xp + (size_t)row * KW + tid * 8);
    d[0] = make_uint4(h[0], l[0], h[1], l[1]);
    d[1] = make_uint4(h[2], l[2], h[3], l[3]);
    d[2] = make_uint4(h[4], l[4], h[5], l[5]);
    d[3] = make_uint4(h[6], l[6], h[7], l[7]);
}

// ---------------- 4) pack active W blocks into per-half fragment streams ----------------
// grid (NGRP, NBK, 2); warp w packs the w-th active ob of entry i in half h.
__global__ void packw_kernel(const float* __restrict__ wt) {
    int g = blockIdx.x, i = blockIdx.y, h = blockIdx.z;
    if (i >= g_knH[g][h]) return;
    int w = threadIdx.x >> 5, lane = threadIdx.x & 31;
    unsigned act = g_actH[g][h][i];
    if (w >= __popc(act)) return;
    int a = nth_bit(act, w);
    int ob = h * 4 + a;
    int kb = g_klistH[g][h][i];
    int slot = (int)g_sbaseH[g][h][i] + w;
    int qr = lane >> 2, qk = (lane & 3) * 2;

    const float* base = wt + (size_t)(g * 128 + ob * 16 + qr) * KDIM + kb * 16 + qk;
    float2 f00 = __ldg((const float2*)base);                   // nt0, k0-7
    float2 f01 = __ldg((const float2*)(base + 8));             // nt0, k8-15
    float2 f10 = __ldg((const float2*)(base + 8 * KDIM));      // nt1, k0-7
    float2 f11 = __ldg((const float2*)(base + 8 * KDIM + 8));  // nt1, k8-15
    unsigned h0, l0, h1, l1, h2, l2, h3, l3;
    cvtpair(f00, h0, l0);
    cvtpair(f01, h1, l1);
    cvtpair(f10, h2, l2);
    cvtpair(f11, h3, l3);
    uint4* dst = g_wfH + ((size_t)(g * 2 + h) * MAXSH + slot) * 64;
    dst[lane]      = make_uint4(h0, h1, h2, h3);
    dst[32 + lane] = make_uint4(l0, l1, l2, l3);
}

// ---------------- 5) block-sparse HMMA GEMM ----------------
// CTA: 128 rows x 128 cols. 8 warps = 4 mw x 2 nw; warp = 32 rows x 4 obs.
// Warp iterates ONLY kbs active in its half. Zero smem, zero cvt, no barriers.
__global__ void __launch_bounds__(256, 2) gemm_kernel(
    const float* __restrict__ bias, float* __restrict__ out)
{
    int tid = threadIdx.x, w = tid >> 5, lane = tid & 31;
    int nw = w & 1, mw = w >> 1;
    int g = blockIdx.x, m0 = blockIdx.y << 7;
    int qr = lane >> 2, q = lane & 3, qk = q * 2;

    float C[2][4][2][4];   // [m-frag][ob'][nt][4]
    #pragma unroll
    for (int mf = 0; mf < 2; mf++)
        #pragma unroll
        for (int a = 0; a < 4; a++)
            #pragma unroll
            for (int nt = 0; nt < 2; nt++)
                #pragma unroll
                for (int qq = 0; qq < 4; qq++) C[mf][a][nt][qq] = 0.0f;

    int kn = g_knH[g][nw];
    int stot = g_stotH[g][nw];
    const unsigned char* klist = g_klistH[g][nw];
    const unsigned char* actL  = g_actH[g][nw];

    // A pair pointers: rows m0 + mw*32 + {qr, qr+8, qr+16, qr+24}, pair col q
    int r0 = m0 + mw * 32 + qr;
    const uint2* pr0 = g_xp + (size_t)r0 * KW + q;
    const uint2* pr1 = pr0 + (size_t)8 * KW;
    const uint2* pr2 = pr0 + (size_t)16 * KW;
    const uint2* pr3 = pr0 + (size_t)24 * KW;
    const uint4* wf = g_wfH + (size_t)(g * 2 + nw) * MAXSH * 64;

    // A regs: [mf][j] j = {r,k0-7},{r+8,k0-7},{r,k8-15},{r+8,k8-15}; .x=hi .y=lo
    uint2 A[8], nA[8];
    uint4 pbh, pbl;
    if (kn > 0) {
        int o = (int)klist[0] * 8;
        A[0] = __ldg(pr0 + o); A[1] = __ldg(pr1 + o);
        A[2] = __ldg(pr0 + o + 4); A[3] = __ldg(pr1 + o + 4);
        A[4] = __ldg(pr2 + o); A[5] = __ldg(pr3 + o);
        A[6] = __ldg(pr2 + o + 4); A[7] = __ldg(pr3 + o + 4);
        pbh = __ldg(wf + lane);
        pbl = __ldg(wf + 32 + lane);
    }

    int t = 0;
    for (int i = 0; i < kn; i++) {
        unsigned act = actL[i];

        // prefetch next entry's A fragments
        if (i + 1 < kn) {
            int no = (int)klist[i + 1] * 8;
            nA[0] = __ldg(pr0 + no); nA[1] = __ldg(pr1 + no);
            nA[2] = __ldg(pr0 + no + 4); nA[3] = __ldg(pr1 + no + 4);
            nA[4] = __ldg(pr2 + no); nA[5] = __ldg(pr3 + no);
            nA[6] = __ldg(pr2 + no + 4); nA[7] = __ldg(pr3 + no + 4);
        }

        #pragma unroll
        for (int a = 0; a < 4; a++) {
            if ((act >> a) & 1) {
                uint4 bh = pbh, bl = pbl;
                if (t + 1 < stot) {
                    pbh = __ldg(wf + (size_t)(t + 1) * 64 + lane);
                    pbl = __ldg(wf + (size_t)(t + 1) * 64 + 32 + lane);
                }
                // m-frag 0
                MMA16816R(C[0][a][0], A[0].x, A[1].x, A[2].x, A[3].x, bh.x, bh.y);
                MMA16816R(C[0][a][0], A[0].y, A[1].y, A[2].y, A[3].y, bh.x, bh.y);
                MMA16816R(C[0][a][0], A[0].x, A[1].x, A[2].x, A[3].x, bl.x, bl.y);
                MMA16816R(C[0][a][1], A[0].x, A[1].x, A[2].x, A[3].x, bh.z, bh.w);
                MMA16816R(C[0][a][1], A[0].y, A[1].y, A[2].y, A[3].y, bh.z, bh.w);
                MMA16816R(C[0][a][1], A[0].x, A[1].x, A[2].x, A[3].x, bl.z, bl.w);
                // m-frag 1
                MMA16816R(C[1][a][0], A[4].x, A[5].x, A[6].x, A[7].x, bh.x, bh.y);
                MMA16816R(C[1][a][0], A[4].y, A[5].y, A[6].y, A[7].y, bh.x, bh.y);
                MMA16816R(C[1][a][0], A[4].x, A[5].x, A[6].x, A[7].x, bl.x, bl.y);
                MMA16816R(C[1][a][1], A[4].x, A[5].x, A[6].x, A[7].x, bh.z, bh.w);
                MMA16816R(C[1][a][1], A[4].y, A[5].y, A[6].y, A[7].y, bh.z, bh.w);
                MMA16816R(C[1][a][1], A[4].x, A[5].x, A[6].x, A[7].x, bl.z, bl.w);
                t++;
            }
        }

        #pragma unroll
        for (int j = 0; j < 8; j++) A[j] = nA[j];
    }

    // ---- epilogue: bias + store ----
    {
        const float* bg = bias + g * 128 + nw * 64;
        #pragma unroll
        for (int mf = 0; mf < 2; mf++) {
            int rr = m0 + mw * 32 + mf * 16 + qr;
            #pragma unroll
            for (int a = 0; a < 4; a++) {
                #pragma unroll
                for (int nt = 0; nt < 2; nt++) {
                    int col = a * 16 + nt * 8 + qk;
                    float2 bv = __ldg((const float2*)(bg + col));
                    size_t gc = (size_t)g * 128 + nw * 64 + col;
                    float2 v0 = make_float2(C[mf][a][nt][0] + bv.x, C[mf][a][nt][1] + bv.y);
                    float2 v1 = make_float2(C[mf][a][nt][2] + bv.x, C[mf][a][nt][3] + bv.y);
                    *(float2*)(out + (size_t)rr * NDIM + gc)       = v0;
                    *(float2*)(out + (size_t)(rr + 8) * NDIM + gc) = v1;
                }
            }
        }
    }
}

// ---------------- launch ----------------
extern "C" void kernel_launch(void* const* d_in, const int* in_sizes, int n_in,
                              void* d_out, int out_size)
{
    const float* x    = (const float*)d_in[0];
    const float* wt   = (const float*)d_in[1];
    const float* bias = (const float*)d_in[2];
    const void*  mask = d_in[3];
    float*       out  = (float*)d_out;

    init_kernel<<<1, 32>>>();
    detect_kernel<<<4096, 256>>>((const unsigned int*)mask);
    build_kernel<<<NGRP, NBK>>>(mask);
    prepx_kernel<<<MTOT, 256>>>(x);
    packw_kernel<<<dim3(NGRP, NBK, 2), 128>>>(wt);
    gemm_kernel<<<dim3(NGRP, MTOT / 128), 256>>>(bias, out);
}

// round 15
// speedup vs baseline: 1.5938x; 1.2995x over previous
#include <cuda_runtime.h>
#include <cuda_bf16.h>
#include <cstdint>
#include <cstddef>

// out[8192,4096] = x[8192,4096] @ (W .* mask)^T + bias  (fp32 in/out)
// R15: HMMA; x stored as per-(mb,kb) FRAGMENT STREAM (lane-contiguous uint4 hi/lo)
// so A loads are 2x LDG.128 contiguous (4 wf) instead of 8 scattered LDG.64 (64 wf).
// Warp tile 32 rows x 4 obs, per-half compacted k-lists, W fragment streams.
#define MTOT 8192
#define KDIM 4096
#define NDIM 4096
#define NBK  256       // 16-wide K blocks
#define NGRP 32        // groups of 8 out-blocks (128 cols each)
#define NMB  512       // 16-row blocks of x
#define MAXSH 1024     // max active blocks per (group, half)

// ---------------- device scratch ----------------
__device__ int           g_flagmask;
__device__ int           g_knH[NGRP][2];
__device__ int           g_stotH[NGRP][2];
__device__ unsigned char g_klistH[NGRP][2][NBK];
__device__ unsigned char g_actH[NGRP][2][NBK];
__device__ short         g_sbaseH[NGRP][2][NBK];
__device__ uint4         g_xf[(size_t)NMB * NBK * 64];         // x fragments, 134MB
__device__ uint4         g_wfH[(size_t)NGRP * 2 * MAXSH * 64]; // W fragments, 64MB

// ---------------- helpers ----------------
static __device__ __forceinline__ void cvtpair(float2 v, unsigned& hi, unsigned& lo) {
    asm("cvt.rn.bf16x2.f32 %0, %1, %2;" : "=r"(hi) : "f"(v.y), "f"(v.x));
    float h0 = __uint_as_float(hi << 16);
    float h1 = __uint_as_float(hi & 0xFFFF0000u);
    float l0 = v.x - h0;
    float l1 = v.y - h1;
    asm("cvt.rn.bf16x2.f32 %0, %1, %2;" : "=r"(lo) : "f"(l1), "f"(l0));
}
static __device__ __forceinline__ int nth_bit(unsigned m, int n) {
    for (int j = 0; j < n; j++) m &= m - 1;
    return __ffs(m) - 1;
}
#define MMA16816R(c, a0, a1, a2, a3, b0, b1) \
    asm volatile("mma.sync.aligned.m16n8k16.row.col.f32.bf16.bf16.f32 " \
        "{%0,%1,%2,%3},{%4,%5,%6,%7},{%8,%9},{%0,%1,%2,%3};" \
        : "+f"((c)[0]), "+f"((c)[1]), "+f"((c)[2]), "+f"((c)[3]) \
        : "r"(a0), "r"(a1), "r"(a2), "r"(a3), "r"(b0), "r"(b1))

// ---------------- 0) reset flags ----------------
__global__ void init_kernel() { if (threadIdx.x == 0) g_flagmask = 0; }

// ---------------- 1) mask dtype detection (4MB window) ----------------
__global__ void detect_kernel(const unsigned int* __restrict__ m) {
    unsigned int w = m[(size_t)blockIdx.x * blockDim.x + threadIdx.x];
    unsigned int f = 0u;
    if (w == 0x3F800000u) f |= 1u;
    if (w == 0x3F803F80u) f |= 2u;
    if (w == 0x01010101u) f |= 4u;
    if (w == 0x00000001u) f |= 8u;
    f = __reduce_or_sync(0xFFFFFFFFu, f);
    __shared__ unsigned int sf;
    if (threadIdx.x == 0) sf = 0u;
    __syncthreads();
    if ((threadIdx.x & 31) == 0 && f) atomicOr(&sf, f);
    __syncthreads();
    if (threadIdx.x == 0 && sf) atomicOr((unsigned int*)&g_flagmask, (int)sf);
}

// ---------------- 2) build per-half compacted lists ----------------
__global__ void build_kernel(const void* __restrict__ mask) {
    int g = blockIdx.x, kb = threadIdx.x;
    int fl = g_flagmask;
    unsigned m = 0;
    for (int a = 0; a < 8; a++) {
        size_t e = (size_t)((g * 8 + a) * 16) * KDIM + (size_t)kb * 16;
        bool v;
        if (fl & 1)      v = ((const float*)mask)[e] != 0.0f;
        else if (fl & 2) v = ((const unsigned short*)mask)[e] != 0;
        else if (fl & 4) v = ((const unsigned char*)mask)[e] != 0;
        else             v = ((const int*)mask)[e] != 0;
        if (v) m |= 1u << a;
    }
    __shared__ unsigned sact[NBK];
    sact[kb] = m;
    __syncthreads();
    if (kb == 0) {
        for (int h = 0; h < 2; h++) {
            int n = 0, s = 0;
            #pragma unroll 1
            for (int k = 0; k < NBK; k++) {
                unsigned ah = (sact[k] >> (h * 4)) & 0xFu;
                if (ah) {
                    g_klistH[g][h][n] = (unsigned char)k;
                    g_actH[g][h][n]   = (unsigned char)ah;
                    g_sbaseH[g][h][n] = (short)s;
                    s += __popc(ah);
                    n++;
                }
            }
            g_knH[g][h] = n;
            g_stotH[g][h] = s;
        }
    }
}

// ---------------- 3) prepx: x -> fragment stream ----------------
// grid (NMB, 32), block 256: warp w handles (mb, kb = by*8 + w).
// Lane (qr = lane>>2, q = lane&3) computes its mma A regs for this (mb,kb):
//   a0=(r,k0-7) a1=(r+8,k0-7) a2=(r,k8-15) a3=(r+8,k8-15), r = mb*16+qr, kpair q.
__global__ void prepx_kernel(const float* __restrict__ x) {
    int mb = blockIdx.x;
    int kb = blockIdx.y * 8 + (threadIdx.x >> 5);
    int lane = threadIdx.x & 31;
    int qr = lane >> 2, qk = (lane & 3) * 2;

    const float* base = x + (size_t)(mb * 16 + qr) * KDIM + kb * 16 + qk;
    float2 f0 = __ldg((const float2*)base);                 // (r, k0-7)
    float2 f1 = __ldg((const float2*)(base + 8 * KDIM));    // (r+8, k0-7)
    float2 f2 = __ldg((const float2*)(base + 8));           // (r, k8-15)
    float2 f3 = __ldg((const float2*)(base + 8 * KDIM + 8));// (r+8, k8-15)
    unsigned h0, l0, h1, l1, h2, l2, h3, l3;
    cvtpair(f0, h0, l0);
    cvtpair(f1, h1, l1);
    cvtpair(f2, h2, l2);
    cvtpair(f3, h3, l3);
    uint4* dst = g_xf + ((size_t)mb * NBK + kb) * 64;
    dst[lane]      = make_uint4(h0, h1, h2, h3);
    dst[32 + lane] = make_uint4(l0, l1, l2, l3);
}

// ---------------- 4) packw: active W blocks -> per-half fragment streams ----------------
__global__ void packw_kernel(const float* __restrict__ wt) {
    int g = blockIdx.x, i = blockIdx.y, h = blockIdx.z;
    if (i >= g_knH[g][h]) return;
    int w = threadIdx.x >> 5, lane = threadIdx.x & 31;
    unsigned act = g_actH[g][h][i];
    if (w >= __popc(act)) return;
    int a = nth_bit(act, w);
    int ob = h * 4 + a;
    int kb = g_klistH[g][h][i];
    int slot = (int)g_sbaseH[g][h][i] + w;
    int qr = lane >> 2, qk = (lane & 3) * 2;

    const float* base = wt + (size_t)(g * 128 + ob * 16 + qr) * KDIM + kb * 16 + qk;
    float2 f00 = __ldg((const float2*)base);
    float2 f01 = __ldg((const float2*)(base + 8));
    float2 f10 = __ldg((const float2*)(base + 8 * KDIM));
    float2 f11 = __ldg((const float2*)(base + 8 * KDIM + 8));
    unsigned h0, l0, h1, l1, h2, l2, h3, l3;
    cvtpair(f00, h0, l0);
    cvtpair(f01, h1, l1);
    cvtpair(f10, h2, l2);
    cvtpair(f11, h3, l3);
    uint4* dst = g_wfH + ((size_t)(g * 2 + h) * MAXSH + slot) * 64;
    dst[lane]      = make_uint4(h0, h1, h2, h3);
    dst[32 + lane] = make_uint4(l0, l1, l2, l3);
}

// ---------------- 5) block-sparse HMMA GEMM ----------------
// CTA: 128 rows x 128 cols. 8 warps = 4 mw x 2 nw; warp = 32 rows x 4 obs.
// A: fragment-stream LDG.128 (contiguous). B: per-half fragment stream, depth-1.
__global__ void __launch_bounds__(256, 2) gemm_kernel(
    const float* __restrict__ bias, float* __restrict__ out)
{
    int tid = threadIdx.x, w = tid >> 5, lane = tid & 31;
    int nw = w & 1, mw = w >> 1;
    int g = blockIdx.x, m0 = blockIdx.y << 7;
    int qr = lane >> 2, qk = (lane & 3) * 2;

    float C[2][4][2][4];
    #pragma unroll
    for (int mf = 0; mf < 2; mf++)
        #pragma unroll
        for (int a = 0; a < 4; a++)
            #pragma unroll
            for (int nt = 0; nt < 2; nt++)
                #pragma unroll
                for (int qq = 0; qq < 4; qq++) C[mf][a][nt][qq] = 0.0f;

    int kn = g_knH[g][nw];
    int stot = g_stotH[g][nw];
    const unsigned char* klist = g_klistH[g][nw];
    const unsigned char* actL  = g_actH[g][nw];

    int mb0 = (m0 >> 4) + mw * 2;
    const uint4* xa0 = g_xf + (size_t)mb0 * NBK * 64 + lane;         // + kb*64 (+32 lo)
    const uint4* xa1 = g_xf + (size_t)(mb0 + 1) * NBK * 64 + lane;
    const uint4* wf  = g_wfH + (size_t)(g * 2 + nw) * MAXSH * 64;

    uint4 Ah0, Al0, Ah1, Al1, nAh0, nAl0, nAh1, nAl1;
    uint4 pbh, pbl;
    if (kn > 0) {
        int o = (int)klist[0] * 64;
        Ah0 = __ldg(xa0 + o); Al0 = __ldg(xa0 + o + 32);
        Ah1 = __ldg(xa1 + o); Al1 = __ldg(xa1 + o + 32);
        pbh = __ldg(wf + lane);
        pbl = __ldg(wf + 32 + lane);
    }

    int t = 0;
    for (int i = 0; i < kn; i++) {
        unsigned act = actL[i];

        if (i + 1 < kn) {
            int no = (int)klist[i + 1] * 64;
            nAh0 = __ldg(xa0 + no); nAl0 = __ldg(xa0 + no + 32);
            nAh1 = __ldg(xa1 + no); nAl1 = __ldg(xa1 + no + 32);
        }

        #pragma unroll
        for (int a = 0; a < 4; a++) {
            if ((act >> a) & 1) {
                uint4 bh = pbh, bl = pbl;
                if (t + 1 < stot) {
                    pbh = __ldg(wf + (size_t)(t + 1) * 64 + lane);
                    pbl = __ldg(wf + (size_t)(t + 1) * 64 + 32 + lane);
                }
                // m-frag 0
                MMA16816R(C[0][a][0], Ah0.x, Ah0.y, Ah0.z, Ah0.w, bh.x, bh.y);
                MMA16816R(C[0][a][0], Al0.x, Al0.y, Al0.z, Al0.w, bh.x, bh.y);
                MMA16816R(C[0][a][0], Ah0.x, Ah0.y, Ah0.z, Ah0.w, bl.x, bl.y);
                MMA16816R(C[0][a][1], Ah0.x, Ah0.y, Ah0.z, Ah0.w, bh.z, bh.w);
                MMA16816R(C[0][a][1], Al0.x, Al0.y, Al0.z, Al0.w, bh.z, bh.w);
                MMA16816R(C[0][a][1], Ah0.x, Ah0.y, Ah0.z, Ah0.w, bl.z, bl.w);
                // m-frag 1
                MMA16816R(C[1][a][0], Ah1.x, Ah1.y, Ah1.z, Ah1.w, bh.x, bh.y);
                MMA16816R(C[1][a][0], Al1.x, Al1.y, Al1.z, Al1.w, bh.x, bh.y);
                MMA16816R(C[1][a][0], Ah1.x, Ah1.y, Ah1.z, Ah1.w, bl.x, bl.y);
                MMA16816R(C[1][a][1], Ah1.x, Ah1.y, Ah1.z, Ah1.w, bh.z, bh.w);
                MMA16816R(C[1][a][1], Al1.x, Al1.y, Al1.z, Al1.w, bh.z, bh.w);
                MMA16816R(C[1][a][1], Ah1.x, Ah1.y, Ah1.z, Ah1.w, bl.z, bl.w);
                t++;
            }
        }

        Ah0 = nAh0; Al0 = nAl0; Ah1 = nAh1; Al1 = nAl1;
    }

    // ---- epilogue: bias + store ----
    {
        const float* bg = bias + g * 128 + nw * 64;
        #pragma unroll
        for (int mf = 0; mf < 2; mf++) {
            int rr = m0 + mw * 32 + mf * 16 + qr;
            #pragma unroll
            for (int a = 0; a < 4; a++) {
                #pragma unroll
                for (int nt = 0; nt < 2; nt++) {
                    int col = a * 16 + nt * 8 + qk;
                    float2 bv = __ldg((const float2*)(bg + col));
                    size_t gc = (size_t)g * 128 + nw * 64 + col;
                    float2 v0 = make_float2(C[mf][a][nt][0] + bv.x, C[mf][a][nt][1] + bv.y);
                    float2 v1 = make_float2(C[mf][a][nt][2] + bv.x, C[mf][a][nt][3] + bv.y);
                    *(float2*)(out + (size_t)rr * NDIM + gc)       = v0;
                    *(float2*)(out + (size_t)(rr + 8) * NDIM + gc) = v1;
                }
            }
        }
    }
}

// ---------------- launch ----------------
extern "C" void kernel_launch(void* const* d_in, const int* in_sizes, int n_in,
                              void* d_out, int out_size)
{
    const float* x    = (const float*)d_in[0];
    const float* wt   = (const float*)d_in[1];
    const float* bias = (const float*)d_in[2];
    const void*  mask = d_in[3];
    float*       out  = (float*)d_out;

    init_kernel<<<1, 32>>>();
    detect_kernel<<<4096, 256>>>((const unsigned int*)mask);
    build_kernel<<<NGRP, NBK>>>(mask);
    prepx_kernel<<<dim3(NMB, 32), 256>>>(x);
    packw_kernel<<<dim3(NGRP, NBK, 2), 128>>>(wt);
    gemm_kernel<<<dim3(NGRP, MTOT / 128), 256>>>(bias, out);
}

// round 16
// speedup vs baseline: 2.4321x; 1.5260x over previous
#include <cuda_runtime.h>
#include <cuda_fp16.h>
#include <cstdint>
#include <cstddef>

// out[8192,4096] = x[8192,4096] @ (W .* mask)^T + bias  (fp32 in/out)
// R16: fp16 HMMA. x = single fp16 fragment stream (halves A L2 traffic);
// W = fp16 hi + fp16 lo (residual) fragment streams. 8 MMAs per active ob.
// Warp tile 32 rows x 4 obs, per-half compacted k-lists. Zero smem GEMM.
#define MTOT 8192
#define KDIM 4096
#define NDIM 4096
#define NBK  256
#define NGRP 32
#define NMB  512
#define MAXSH 1024

// ---------------- device scratch ----------------
__device__ int           g_flagmask;
__device__ int           g_knH[NGRP][2];
__device__ int           g_stotH[NGRP][2];
__device__ unsigned char g_klistH[NGRP][2][NBK];
__device__ unsigned char g_actH[NGRP][2][NBK];
__device__ short         g_sbaseH[NGRP][2][NBK];
__device__ uint4         g_xf[(size_t)NMB * NBK * 32];         // x fp16 fragments, 67MB
__device__ uint4         g_wfH[(size_t)NGRP * 2 * MAXSH * 64]; // W fp16 hi/lo fragments, 64MB

// ---------------- helpers ----------------
static __device__ __forceinline__ unsigned f16pack(float2 v) {
    __half2 h = __float22half2_rn(v);
    return *(unsigned*)&h;
}
static __device__ __forceinline__ void f16split(float2 v, unsigned& hi, unsigned& lo) {
    __half2 h = __float22half2_rn(v);
    float2 hf = __half22float2(h);
    __half2 l = __float22half2_rn(make_float2(v.x - hf.x, v.y - hf.y));
    hi = *(unsigned*)&h;
    lo = *(unsigned*)&l;
}
static __device__ __forceinline__ int nth_bit(unsigned m, int n) {
    for (int j = 0; j < n; j++) m &= m - 1;
    return __ffs(m) - 1;
}
#define MMAF16(c, a0, a1, a2, a3, b0, b1) \
    asm volatile("mma.sync.aligned.m16n8k16.row.col.f32.f16.f16.f32 " \
        "{%0,%1,%2,%3},{%4,%5,%6,%7},{%8,%9},{%0,%1,%2,%3};" \
        : "+f"((c)[0]), "+f"((c)[1]), "+f"((c)[2]), "+f"((c)[3]) \
        : "r"(a0), "r"(a1), "r"(a2), "r"(a3), "r"(b0), "r"(b1))

// ---------------- 0) reset flags ----------------
__global__ void init_kernel() { if (threadIdx.x == 0) g_flagmask = 0; }

// ---------------- 1) mask dtype detection (4MB window) ----------------
__global__ void detect_kernel(const unsigned int* __restrict__ m) {
    unsigned int w = m[(size_t)blockIdx.x * blockDim.x + threadIdx.x];
    unsigned int f = 0u;
    if (w == 0x3F800000u) f |= 1u;
    if (w == 0x3F803F80u) f |= 2u;
    if (w == 0x01010101u) f |= 4u;
    if (w == 0x00000001u) f |= 8u;
    f = __reduce_or_sync(0xFFFFFFFFu, f);
    __shared__ unsigned int sf;
    if (threadIdx.x == 0) sf = 0u;
    __syncthreads();
    if ((threadIdx.x & 31) == 0 && f) atomicOr(&sf, f);
    __syncthreads();
    if (threadIdx.x == 0 && sf) atomicOr((unsigned int*)&g_flagmask, (int)sf);
}

// ---------------- 2) build per-half compacted lists ----------------
__global__ void build_kernel(const void* __restrict__ mask) {
    int g = blockIdx.x, kb = threadIdx.x;
    int fl = g_flagmask;
    unsigned m = 0;
    for (int a = 0; a < 8; a++) {
        size_t e = (size_t)((g * 8 + a) * 16) * KDIM + (size_t)kb * 16;
        bool v;
        if (fl & 1)      v = ((const float*)mask)[e] != 0.0f;
        else if (fl & 2) v = ((const unsigned short*)mask)[e] != 0;
        else if (fl & 4) v = ((const unsigned char*)mask)[e] != 0;
        else             v = ((const int*)mask)[e] != 0;
        if (v) m |= 1u << a;
    }
    __shared__ unsigned sact[NBK];
    sact[kb] = m;
    __syncthreads();
    if (kb == 0) {
        for (int h = 0; h < 2; h++) {
            int n = 0, s = 0;
            #pragma unroll 1
            for (int k = 0; k < NBK; k++) {
                unsigned ah = (sact[k] >> (h * 4)) & 0xFu;
                if (ah) {
                    g_klistH[g][h][n] = (unsigned char)k;
                    g_actH[g][h][n]   = (unsigned char)ah;
                    g_sbaseH[g][h][n] = (short)s;
                    s += __popc(ah);
                    n++;
                }
            }
            g_knH[g][h] = n;
            g_stotH[g][h] = s;
        }
    }
}

// ---------------- 3) prepx: x -> single fp16 fragment stream ----------------
// grid (NMB, 32), block 256: warp w handles (mb, kb = by*8 + w).
// Lane regs a0..a3 = (r,k0-7),(r+8,k0-7),(r,k8-15),(r+8,k8-15); r=mb*16+qr.
__global__ void prepx_kernel(const float* __restrict__ x) {
    int mb = blockIdx.x;
    int kb = blockIdx.y * 8 + (threadIdx.x >> 5);
    int lane = threadIdx.x & 31;
    int qr = lane >> 2, qk = (lane & 3) * 2;

    const float* base = x + (size_t)(mb * 16 + qr) * KDIM + kb * 16 + qk;
    float2 f0 = __ldg((const float2*)base);
    float2 f1 = __ldg((const float2*)(base + 8 * KDIM));
    float2 f2 = __ldg((const float2*)(base + 8));
    float2 f3 = __ldg((const float2*)(base + 8 * KDIM + 8));
    uint4* dst = g_xf + ((size_t)mb * NBK + kb) * 32;
    dst[lane] = make_uint4(f16pack(f0), f16pack(f1), f16pack(f2), f16pack(f3));
}

// ---------------- 4) packw: active W blocks -> fp16 hi/lo fragment streams ----------------
__global__ void packw_kernel(const float* __restrict__ wt) {
    int g = blockIdx.x, i = blockIdx.y, h = blockIdx.z;
    if (i >= g_knH[g][h]) return;
    int w = threadIdx.x >> 5, lane = threadIdx.x & 31;
    unsigned act = g_actH[g][h][i];
    if (w >= __popc(act)) return;
    int a = nth_bit(act, w);
    int ob = h * 4 + a;
    int kb = g_klistH[g][h][i];
    int slot = (int)g_sbaseH[g][h][i] + w;
    int qr = lane >> 2, qk = (lane & 3) * 2;

    const float* base = wt + (size_t)(g * 128 + ob * 16 + qr) * KDIM + kb * 16 + qk;
    float2 f00 = __ldg((const float2*)base);                   // nt0, k0-7
    float2 f01 = __ldg((const float2*)(base + 8));             // nt0, k8-15
    float2 f10 = __ldg((const float2*)(base + 8 * KDIM));      // nt1, k0-7
    float2 f11 = __ldg((const float2*)(base + 8 * KDIM + 8));  // nt1, k8-15
    unsigned h0, l0, h1, l1, h2, l2, h3, l3;
    f16split(f00, h0, l0);
    f16split(f01, h1, l1);
    f16split(f10, h2, l2);
    f16split(f11, h3, l3);
    uint4* dst = g_wfH + ((size_t)(g * 2 + h) * MAXSH + slot) * 64;
    dst[lane]      = make_uint4(h0, h1, h2, h3);
    dst[32 + lane] = make_uint4(l0, l1, l2, l3);
}

// ---------------- 5) block-sparse fp16 HMMA GEMM ----------------
// CTA: 128 rows x 128 cols. 8 warps = 4 mw x 2 nw; warp = 32 rows x 4 obs.
__global__ void __launch_bounds__(256, 2) gemm_kernel(
    const float* __restrict__ bias, float* __restrict__ out)
{
    int tid = threadIdx.x, w = tid >> 5, lane = tid & 31;
    int nw = w & 1, mw = w >> 1;
    int g = blockIdx.x, m0 = blockIdx.y << 7;
    int qr = lane >> 2, qk = (lane & 3) * 2;

    float C[2][4][2][4];
    #pragma unroll
    for (int mf = 0; mf < 2; mf++)
        #pragma unroll
        for (int a = 0; a < 4; a++)
            #pragma unroll
            for (int nt = 0; nt < 2; nt++)
                #pragma unroll
                for (int qq = 0; qq < 4; qq++) C[mf][a][nt][qq] = 0.0f;

    int kn = g_knH[g][nw];
    int stot = g_stotH[g][nw];
    const unsigned char* klist = g_klistH[g][nw];
    const unsigned char* actL  = g_actH[g][nw];

    int mb0 = (m0 >> 4) + mw * 2;
    const uint4* xa0 = g_xf + (size_t)mb0 * NBK * 32 + lane;
    const uint4* xa1 = g_xf + (size_t)(mb0 + 1) * NBK * 32 + lane;
    const uint4* wf  = g_wfH + (size_t)(g * 2 + nw) * MAXSH * 64;

    uint4 A0, A1, nA0, nA1;
    uint4 pbh, pbl;
    if (kn > 0) {
        int o = (int)klist[0] * 32;
        A0 = __ldg(xa0 + o);
        A1 = __ldg(xa1 + o);
        pbh = __ldg(wf + lane);
        pbl = __ldg(wf + 32 + lane);
    }

    int t = 0;
    for (int i = 0; i < kn; i++) {
        unsigned act = actL[i];

        if (i + 1 < kn) {
            int no = (int)klist[i + 1] * 32;
            nA0 = __ldg(xa0 + no);
            nA1 = __ldg(xa1 + no);
        }

        #pragma unroll
        for (int a = 0; a < 4; a++) {
            if ((act >> a) & 1) {
                uint4 bh = pbh, bl = pbl;
                if (t + 1 < stot) {
                    pbh = __ldg(wf + (size_t)(t + 1) * 64 + lane);
                    pbl = __ldg(wf + (size_t)(t + 1) * 64 + 32 + lane);
                }
                // m-frag 0
                MMAF16(C[0][a][0], A0.x, A0.y, A0.z, A0.w, bh.x, bh.y);
                MMAF16(C[0][a][0], A0.x, A0.y, A0.z, A0.w, bl.x, bl.y);
                MMAF16(C[0][a][1], A0.x, A0.y, A0.z, A0.w, bh.z, bh.w);
                MMAF16(C[0][a][1], A0.x, A0.y, A0.z, A0.w, bl.z, bl.w);
                // m-frag 1
                MMAF16(C[1][a][0], A1.x, A1.y, A1.z, A1.w, bh.x, bh.y);
                MMAF16(C[1][a][0], A1.x, A1.y, A1.z, A1.w, bl.x, bl.y);
                MMAF16(C[1][a][1], A1.x, A1.y, A1.z, A1.w, bh.z, bh.w);
                MMAF16(C[1][a][1], A1.x, A1.y, A1.z, A1.w, bl.z, bl.w);
                t++;
            }
        }

        A0 = nA0; A1 = nA1;
    }

    // ---- epilogue: bias + store ----
    {
        const float* bg = bias + g * 128 + nw * 64;
        #pragma unroll
        for (int mf = 0; mf < 2; mf++) {
            int rr = m0 + mw * 32 + mf * 16 + qr;
            #pragma unroll
            for (int a = 0; a < 4; a++) {
                #pragma unroll
                for (int nt = 0; nt < 2; nt++) {
                    int col = a * 16 + nt * 8 + qk;
                    float2 bv = __ldg((const float2*)(bg + col));
                    size_t gc = (size_t)g * 128 + nw * 64 + col;
                    float2 v0 = make_float2(C[mf][a][nt][0] + bv.x, C[mf][a][nt][1] + bv.y);
                    float2 v1 = make_float2(C[mf][a][nt][2] + bv.x, C[mf][a][nt][3] + bv.y);
                    *(float2*)(out + (size_t)rr * NDIM + gc)       = v0;
                    *(float2*)(out + (size_t)(rr + 8) * NDIM + gc) = v1;
                }
            }
        }
    }
}

// ---------------- launch ----------------
extern "C" void kernel_launch(void* const* d_in, const int* in_sizes, int n_in,
                              void* d_out, int out_size)
{
    const float* x    = (const float*)d_in[0];
    const float* wt   = (const float*)d_in[1];
    const float* bias = (const float*)d_in[2];
    const void*  mask = d_in[3];
    float*       out  = (float*)d_out;

    init_kernel<<<1, 32>>>();
    detect_kernel<<<4096, 256>>>((const unsigned int*)mask);
    build_kernel<<<NGRP, NBK>>>(mask);
    prepx_kernel<<<dim3(NMB, 32), 256>>>(x);
    packw_kernel<<<dim3(NGRP, NBK, 2), 128>>>(wt);
    gemm_kernel<<<dim3(NGRP, MTOT / 128), 256>>>(bias, out);
}

// round 17
// speedup vs baseline: 2.5624x; 1.0536x over previous
#include <cuda_runtime.h>
#include <cuda_fp16.h>
#include <cstdint>
#include <cstddef>

// out[8192,4096] = x[8192,4096] @ (W .* mask)^T + bias  (fp32 in/out)
// R17: fp16 HMMA both operands single-precision-fp16 (4 MMAs per active ob).
// x and W as per-(block) fragment streams; per-half compacted k-lists;
// warp tile 32 rows x 4 obs. Zero smem GEMM, no barriers.
#define MTOT 8192
#define KDIM 4096
#define NDIM 4096
#define NBK  256
#define NGRP 32
#define NMB  512
#define MAXSH 1024

// ---------------- device scratch ----------------
__device__ int           g_flagmask;
__device__ int           g_knH[NGRP][2];
__device__ int           g_stotH[NGRP][2];
__device__ unsigned char g_klistH[NGRP][2][NBK];
__device__ unsigned char g_actH[NGRP][2][NBK];
__device__ short         g_sbaseH[NGRP][2][NBK];
__device__ uint4         g_xf[(size_t)NMB * NBK * 32];         // x fp16 fragments, 67MB
__device__ uint4         g_wfH[(size_t)NGRP * 2 * MAXSH * 32]; // W fp16 fragments, 32MB

// ---------------- helpers ----------------
static __device__ __forceinline__ unsigned f16pack(float2 v) {
    __half2 h = __float22half2_rn(v);
    return *(unsigned*)&h;
}
static __device__ __forceinline__ int nth_bit(unsigned m, int n) {
    for (int j = 0; j < n; j++) m &= m - 1;
    return __ffs(m) - 1;
}
#define MMAF16(c, a0, a1, a2, a3, b0, b1) \
    asm volatile("mma.sync.aligned.m16n8k16.row.col.f32.f16.f16.f32 " \
        "{%0,%1,%2,%3},{%4,%5,%6,%7},{%8,%9},{%0,%1,%2,%3};" \
        : "+f"((c)[0]), "+f"((c)[1]), "+f"((c)[2]), "+f"((c)[3]) \
        : "r"(a0), "r"(a1), "r"(a2), "r"(a3), "r"(b0), "r"(b1))

// ---------------- 0) reset flags ----------------
__global__ void init_kernel() { if (threadIdx.x == 0) g_flagmask = 0; }

// ---------------- 1) mask dtype detection (4MB window) ----------------
__global__ void detect_kernel(const unsigned int* __restrict__ m) {
    unsigned int w = m[(size_t)blockIdx.x * blockDim.x + threadIdx.x];
    unsigned int f = 0u;
    if (w == 0x3F800000u) f |= 1u;
    if (w == 0x3F803F80u) f |= 2u;
    if (w == 0x01010101u) f |= 4u;
    if (w == 0x00000001u) f |= 8u;
    f = __reduce_or_sync(0xFFFFFFFFu, f);
    __shared__ unsigned int sf;
    if (threadIdx.x == 0) sf = 0u;
    __syncthreads();
    if ((threadIdx.x & 31) == 0 && f) atomicOr(&sf, f);
    __syncthreads();
    if (threadIdx.x == 0 && sf) atomicOr((unsigned int*)&g_flagmask, (int)sf);
}

// ---------------- 2) build per-half compacted lists ----------------
__global__ void build_kernel(const void* __restrict__ mask) {
    int g = blockIdx.x, kb = threadIdx.x;
    int fl = g_flagmask;
    unsigned m = 0;
    for (int a = 0; a < 8; a++) {
        size_t e = (size_t)((g * 8 + a) * 16) * KDIM + (size_t)kb * 16;
        bool v;
        if (fl & 1)      v = ((const float*)mask)[e] != 0.0f;
        else if (fl & 2) v = ((const unsigned short*)mask)[e] != 0;
        else if (fl & 4) v = ((const unsigned char*)mask)[e] != 0;
        else             v = ((const int*)mask)[e] != 0;
        if (v) m |= 1u << a;
    }
    __shared__ unsigned sact[NBK];
    sact[kb] = m;
    __syncthreads();
    if (kb == 0) {
        for (int h = 0; h < 2; h++) {
            int n = 0, s = 0;
            #pragma unroll 1
            for (int k = 0; k < NBK; k++) {
                unsigned ah = (sact[k] >> (h * 4)) & 0xFu;
                if (ah) {
                    g_klistH[g][h][n] = (unsigned char)k;
                    g_actH[g][h][n]   = (unsigned char)ah;
                    g_sbaseH[g][h][n] = (short)s;
                    s += __popc(ah);
                    n++;
                }
            }
            g_knH[g][h] = n;
            g_stotH[g][h] = s;
        }
    }
}

// ---------------- 3) prepx: x -> single fp16 fragment stream ----------------
__global__ void prepx_kernel(const float* __restrict__ x) {
    int mb = blockIdx.x;
    int kb = blockIdx.y * 8 + (threadIdx.x >> 5);
    int lane = threadIdx.x & 31;
    int qr = lane >> 2, qk = (lane & 3) * 2;

    const float* base = x + (size_t)(mb * 16 + qr) * KDIM + kb * 16 + qk;
    float2 f0 = __ldg((const float2*)base);
    float2 f1 = __ldg((const float2*)(base + 8 * KDIM));
    float2 f2 = __ldg((const float2*)(base + 8));
    float2 f3 = __ldg((const float2*)(base + 8 * KDIM + 8));
    uint4* dst = g_xf + ((size_t)mb * NBK + kb) * 32;
    dst[lane] = make_uint4(f16pack(f0), f16pack(f1), f16pack(f2), f16pack(f3));
}

// ---------------- 4) packw: active W blocks -> fp16 fragment streams ----------------
__global__ void packw_kernel(const float* __restrict__ wt) {
    int g = blockIdx.x, i = blockIdx.y, h = blockIdx.z;
    if (i >= g_knH[g][h]) return;
    int w = threadIdx.x >> 5, lane = threadIdx.x & 31;
    unsigned act = g_actH[g][h][i];
    if (w >= __popc(act)) return;
    int a = nth_bit(act, w);
    int ob = h * 4 + a;
    int kb = g_klistH[g][h][i];
    int slot = (int)g_sbaseH[g][h][i] + w;
    int qr = lane >> 2, qk = (lane & 3) * 2;

    const float* base = wt + (size_t)(g * 128 + ob * 16 + qr) * KDIM + kb * 16 + qk;
    float2 f00 = __ldg((const float2*)base);                   // nt0, k0-7
    float2 f01 = __ldg((const float2*)(base + 8));             // nt0, k8-15
    float2 f10 = __ldg((const float2*)(base + 8 * KDIM));      // nt1, k0-7
    float2 f11 = __ldg((const float2*)(base + 8 * KDIM + 8));  // nt1, k8-15
    uint4* dst = g_wfH + ((size_t)(g * 2 + h) * MAXSH + slot) * 32;
    dst[lane] = make_uint4(f16pack(f00), f16pack(f01), f16pack(f10), f16pack(f11));
}

// ---------------- 5) block-sparse fp16 HMMA GEMM ----------------
// CTA: 128 rows x 128 cols. 8 warps = 4 mw x 2 nw; warp = 32 rows x 4 obs.
__global__ void __launch_bounds__(256, 2) gemm_kernel(
    const float* __restrict__ bias, float* __restrict__ out)
{
    int tid = threadIdx.x, w = tid >> 5, lane = tid & 31;
    int nw = w & 1, mw = w >> 1;
    int g = blockIdx.x, m0 = blockIdx.y << 7;
    int qr = lane >> 2, qk = (lane & 3) * 2;

    float C[2][4][2][4];
    #pragma unroll
    for (int mf = 0; mf < 2; mf++)
        #pragma unroll
        for (int a = 0; a < 4; a++)
            #pragma unroll
            for (int nt = 0; nt < 2; nt++)
                #pragma unroll
                for (int qq = 0; qq < 4; qq++) C[mf][a][nt][qq] = 0.0f;

    int kn = g_knH[g][nw];
    int stot = g_stotH[g][nw];
    const unsigned char* klist = g_klistH[g][nw];
    const unsigned char* actL  = g_actH[g][nw];

    int mb0 = (m0 >> 4) + mw * 2;
    const uint4* xa0 = g_xf + (size_t)mb0 * NBK * 32 + lane;
    const uint4* xa1 = g_xf + (size_t)(mb0 + 1) * NBK * 32 + lane;
    const uint4* wf  = g_wfH + (size_t)(g * 2 + nw) * MAXSH * 32;

    uint4 A0, A1, nA0, nA1;
    uint4 pb;
    if (kn > 0) {
        int o = (int)klist[0] * 32;
        A0 = __ldg(xa0 + o);
        A1 = __ldg(xa1 + o);
        pb = __ldg(wf + lane);
    }

    int t = 0;
    for (int i = 0; i < kn; i++) {
        unsigned act = actL[i];

        if (i + 1 < kn) {
            int no = (int)klist[i + 1] * 32;
            nA0 = __ldg(xa0 + no);
            nA1 = __ldg(xa1 + no);
        }

        #pragma unroll
        for (int a = 0; a < 4; a++) {
            if ((act >> a) & 1) {
                uint4 b = pb;
                if (t + 1 < stot) {
                    pb = __ldg(wf + (size_t)(t + 1) * 32 + lane);
                }
                MMAF16(C[0][a][0], A0.x, A0.y, A0.z, A0.w, b.x, b.y);
                MMAF16(C[0][a][1], A0.x, A0.y, A0.z, A0.w, b.z, b.w);
                MMAF16(C[1][a][0], A1.x, A1.y, A1.z, A1.w, b.x, b.y);
                MMAF16(C[1][a][1], A1.x, A1.y, A1.z, A1.w, b.z, b.w);
                t++;
            }
        }

        A0 = nA0; A1 = nA1;
    }

    // ---- epilogue: bias + store ----
    {
        const float* bg = bias + g * 128 + nw * 64;
        #pragma unroll
        for (int mf = 0; mf < 2; mf++) {
            int rr = m0 + mw * 32 + mf * 16 + qr;
            #pragma unroll
            for (int a = 0; a < 4; a++) {
                #pragma unroll
                for (int nt = 0; nt < 2; nt++) {
                    int col = a * 16 + nt * 8 + qk;
                    float2 bv = __ldg((const float2*)(bg + col));
                    size_t gc = (size_t)g * 128 + nw * 64 + col;
                    float2 v0 = make_float2(C[mf][a][nt][0] + bv.x, C[mf][a][nt][1] + bv.y);
                    float2 v1 = make_float2(C[mf][a][nt][2] + bv.x, C[mf][a][nt][3] + bv.y);
                    *(float2*)(out + (size_t)rr * NDIM + gc)       = v0;
                    *(float2*)(out + (size_t)(rr + 8) * NDIM + gc) = v1;
                }
            }
        }
    }
}

// ---------------- launch ----------------
extern "C" void kernel_launch(void* const* d_in, const int* in_sizes, int n_in,
                              void* d_out, int out_size)
{
    const float* x    = (const float*)d_in[0];
    const float* wt   = (const float*)d_in[1];
    const float* bias = (const float*)d_in[2];
    const void*  mask = d_in[3];
    float*       out  = (float*)d_out;

    init_kernel<<<1, 32>>>();
    detect_kernel<<<4096, 256>>>((const unsigned int*)mask);
    build_kernel<<<NGRP, NBK>>>(mask);
    prepx_kernel<<<dim3(NMB, 32), 256>>>(x);
    packw_kernel<<<dim3(NGRP, NBK, 2), 128>>>(wt);
    gemm_kernel<<<dim3(NGRP, MTOT / 128), 256>>>(bias, out);
}